// round 11
// baseline (speedup 1.0000x reference)
#include <cuda_runtime.h>
#include <cuda_fp16.h>
#include <mma.h>

using namespace nvcuda;

// Problem constants
#define BB   2048
#define TT   512
#define FF   64
#define HH   16
#define G4   64            // 4*H
#define BT   (BB * TT)     // 1,048,576 rows of x
#define TB   (TT / 4)      // 128 t-blocks of 4 steps

// 128 MiB scratch: xz (+bias) fp16, layout [bpair][tb][row01][gate][4t]
__device__ __half g_xz[(long)BB * G4 * TT];

// ---------------------------------------------------------------------------
// helpers
// ---------------------------------------------------------------------------
typedef unsigned long long u64;
__device__ __forceinline__ u64 pk2(float lo, float hi) {
    u64 r; asm("mov.b64 %0, {%1, %2};" : "=l"(r) : "f"(lo), "f"(hi)); return r;
}
__device__ __forceinline__ float upk_sum(u64 v) {
    float lo, hi; asm("mov.b64 {%0, %1}, %2;" : "=f"(lo), "=f"(hi) : "l"(v));
    return lo + hi;
}
__device__ __forceinline__ u64 ffma2(u64 a, u64 b, u64 c) {
    u64 d; asm("fma.rn.f32x2 %0, %1, %2, %3;" : "=l"(d) : "l"(a), "l"(b), "l"(c));
    return d;
}
__device__ __forceinline__ u64 add2(u64 a, u64 b) {
    u64 d; asm("add.rn.f32x2 %0, %1, %2;" : "=l"(d) : "l"(a), "l"(b));
    return d;
}
__device__ __forceinline__ unsigned smem_u32(const void* p) {
    unsigned a;
    asm("{ .reg .u64 t; cvta.to.shared.u64 t, %1; cvt.u32.u64 %0, t; }"
        : "=r"(a) : "l"(p));
    return a;
}
__device__ __forceinline__ void cp16(unsigned dst, const void* src) {
    asm volatile("cp.async.ca.shared.global [%0], [%1], 16;" :: "r"(dst), "l"(src));
}
#define CP_COMMIT() asm volatile("cp.async.commit_group;" ::: "memory")
#define CP_WAIT0()  asm volatile("cp.async.wait_group 0;" ::: "memory")

// sigmoid(x) = 0.5*tanh(0.5x)+0.5  (1 MUFU op)
__device__ __forceinline__ float sig_t(float x) {
    float t;
    asm("tanh.approx.f32 %0, %1;" : "=f"(t) : "f"(x * 0.5f));
    return fmaf(t, 0.5f, 0.5f);
}

__device__ __forceinline__ void unpack4(uint2 v, float* o) {
    float2 q0 = __half22float2(*(__half2*)&v.x);
    float2 q1 = __half22float2(*(__half2*)&v.y);
    o[0] = q0.x; o[1] = q0.y; o[2] = q1.x; o[3] = q1.y;
}

// ---------------------------------------------------------------------------
// Kernel A: xz = x @ Wx + b (tf32 WMMA), fp16 store to [bpair][tb][row][gate][4t]
// Per block: NTILE 64-row tiles. Wx B-fragments in registers; x double-buffered
// cp.async; per-warp private transpose epilogue (no block syncs in epilogue).
// ---------------------------------------------------------------------------
#define NTILE 16
#define PAD   72   // x staging pad (multiple of 8)
#define ZW_LD 36   // per-warp transpose pad (multiple of 4)
#define SMEM_A_BYTES ((2 * 64 * PAD + 8 * 16 * ZW_LD) * 4)   // 55296 B

__global__ __launch_bounds__(256) void xz_gemm_kernel(
    const float* __restrict__ x, const float* __restrict__ Wx,
    const float* __restrict__ bias)
{
    extern __shared__ float smem[];
    float* xs0 = smem;
    float* xs1 = smem + 64 * PAD;
    float* zw  = smem + 2 * 64 * PAD;   // Wx staging, then per-warp zs strips

    const int tid  = threadIdx.x;
    const int warp = tid >> 5;
    const int lane = tid & 31;
    const int wr   = warp >> 1;   // 0..3 -> 16-row strip
    const int wc   = warp & 1;    // 0..1 -> 32-col half

    // Stage Wx (64x64) once into zw region (PAD stride)
    const float4* wg = (const float4*)Wx;
    #pragma unroll
    for (int i = tid; i < FF * 16; i += 256) {
        int r = i >> 4, c = i & 15;
        float4 v = wg[r * 16 + c];
        // zw region is 4608 floats = 64*72 exactly
        float* dst = &zw[r * PAD + c * 4];
        dst[0] = v.x; dst[1] = v.y; dst[2] = v.z; dst[3] = v.w;
    }
    __syncthreads();

    // Preload all B fragments into registers (tf32)
    wmma::fragment<wmma::matrix_b, 16, 16, 8, wmma::precision::tf32, wmma::row_major> bfr[8][2];
    #pragma unroll
    for (int k = 0; k < 8; k++) {
        #pragma unroll
        for (int n = 0; n < 2; n++) {
            wmma::load_matrix_sync(bfr[k][n], &zw[(k * 8) * PAD + wc * 32 + n * 16], PAD);
            #pragma unroll
            for (int e = 0; e < bfr[k][n].num_elements; e++)
                bfr[k][n].x[e] = wmma::__float_to_tf32(bfr[k][n].x[e]);
        }
    }
    __syncthreads();   // zw free for per-warp reuse

    float* zwp = zw + warp * 16 * ZW_LD;        // this warp's private strip
    const float bg = bias[wc * 32 + lane];      // gate fixed per lane

    const long tile0 = (long)blockIdx.x * NTILE;

    // Prefetch tile 0
    {
        const float* src = x + tile0 * 64 * FF;
        unsigned dbase = smem_u32(xs0);
        #pragma unroll
        for (int j = 0; j < 4; j++) {
            int i = tid + j * 256;
            int r = i >> 4, c = i & 15;
            cp16(dbase + (unsigned)(r * PAD + c * 4) * 4, src + r * 64 + c * 4);
        }
        CP_COMMIT();
    }

    #pragma unroll 1
    for (int it = 0; it < NTILE; it++) {
        CP_WAIT0();
        __syncthreads();   // buffer `it` filled by all; all warps done with buffer it-1

        if (it + 1 < NTILE) {
            const float* src = x + (tile0 + it + 1) * 64 * FF;
            unsigned dbase = smem_u32(((it + 1) & 1) ? xs1 : xs0);
            #pragma unroll
            for (int j = 0; j < 4; j++) {
                int i = tid + j * 256;
                int r = i >> 4, c = i & 15;
                cp16(dbase + (unsigned)(r * PAD + c * 4) * 4, src + r * 64 + c * 4);
            }
            CP_COMMIT();
        }

        float* xb = (it & 1) ? xs1 : xs0;

        wmma::fragment<wmma::accumulator, 16, 16, 8, float> acc[2];
        wmma::fill_fragment(acc[0], 0.0f);
        wmma::fill_fragment(acc[1], 0.0f);

        #pragma unroll
        for (int k = 0; k < 8; k++) {
            wmma::fragment<wmma::matrix_a, 16, 16, 8, wmma::precision::tf32, wmma::row_major> a;
            wmma::load_matrix_sync(a, &xb[(wr * 16) * PAD + k * 8], PAD);
            #pragma unroll
            for (int e = 0; e < a.num_elements; e++) a.x[e] = wmma::__float_to_tf32(a.x[e]);
            wmma::mma_sync(acc[0], a, bfr[k][0], acc[0]);
            wmma::mma_sync(acc[1], a, bfr[k][1], acc[1]);
        }

        // Per-warp private transpose: acc patch = rows wr*16..+16, gates wc*32..+32
        wmma::store_matrix_sync(zwp,      acc[0], ZW_LD, wmma::mem_row_major);
        wmma::store_matrix_sync(zwp + 16, acc[1], ZW_LD, wmma::mem_row_major);
        __syncwarp();

        // fp16 write-out: lane owns gate wc*32+lane; 4 tb chunks of this patch
        {
            const long row0 = (tile0 + it) * 64;
            const int b  = (int)(row0 >> 9);
            const int t0 = (int)(row0 & 511);

            #pragma unroll
            for (int jj = 0; jj < 4; jj++) {
                const long tbg = (t0 >> 2) + wr * 4 + jj;
                __half* chunk = g_xz +
                    (((long)(b >> 1) * TB + tbg) * 2 + (b & 1)) * 256 +
                    (wc * 32 + lane) * 4;
                __half2 h01 = __floats2half2_rn(zwp[(jj * 4 + 0) * ZW_LD + lane] + bg,
                                                zwp[(jj * 4 + 1) * ZW_LD + lane] + bg);
                __half2 h23 = __floats2half2_rn(zwp[(jj * 4 + 2) * ZW_LD + lane] + bg,
                                                zwp[(jj * 4 + 3) * ZW_LD + lane] + bg);
                uint2 v;
                v.x = *(unsigned*)&h01;
                v.y = *(unsigned*)&h23;
                *(uint2*)chunk = v;
            }
        }
        // next store_matrix into zwp is gated by next iteration's __syncthreads
    }
}

// ---------------------------------------------------------------------------
// Kernel B: LSTM recurrence + MLP head. 4 rows per warp (2 bpair chains),
// 1 warp per block. Lane u computes all 4 gates of unit u for row (lane&16)
// of BOTH chains; FFMA2 with 2-way split chains; smem double-slot h broadcast.
// ---------------------------------------------------------------------------
__global__ __launch_bounds__(32) void lstm_rec_kernel(
    const float* __restrict__ Wh,
    const float* __restrict__ W2, const float* __restrict__ b2,
    const float* __restrict__ W3, const float* __restrict__ b3,
    const float* __restrict__ Wo, const float* __restrict__ bo,
    float* __restrict__ out)
{
    __shared__ alignas(8) float hsm[2][2][32];   // [slot][chain][lane]

    const int lane = threadIdx.x;
    const int u    = lane & 15;             // unit
    const int hsel = lane & 16;             // row within pair
    const int p0 = blockIdx.x * 2;          // chain A bpair
    const int p1 = p0 + 1;                  // chain B bpair

    // Packed recurrent weights (shared by all 4 rows): wp[g][m]
    u64 wp[4][8];
    #pragma unroll
    for (int g = 0; g < 4; g++) {
        const int gate = u + 16 * g;
        #pragma unroll
        for (int m = 0; m < 8; m++)
            wp[g][m] = pk2(Wh[(2 * m) * G4 + gate], Wh[(2 * m + 1) * G4 + gate]);
    }

    const __half* baseA = g_xz + (long)p0 * (TB * 512) + (hsel >> 4) * 256 + u * 4;
    const __half* baseB = g_xz + (long)p1 * (TB * 512) + (hsel >> 4) * 256 + u * 4;

    float hA = 0.0f, cA = 0.0f, hB = 0.0f, cB = 0.0f;
    int p = 0;

    uint2 curA[4], nxtA[4], curB[4], nxtB[4];
    #pragma unroll
    for (int m = 0; m < 4; m++) {
        curA[m] = *(const uint2*)(baseA + 64 * m);
        curB[m] = *(const uint2*)(baseB + 64 * m);
    }

    #pragma unroll 1
    for (int tb = 0; tb < TB; tb++) {
        if (tb < TB - 1) {
            const __half* qa = baseA + (tb + 1) * 512;
            const __half* qb = baseB + (tb + 1) * 512;
            #pragma unroll
            for (int m = 0; m < 4; m++) {
                nxtA[m] = *(const uint2*)(qa + 64 * m);
                nxtB[m] = *(const uint2*)(qb + 64 * m);
            }
        }

        float xA[4][4], xB[4][4];   // [gate][k]
        #pragma unroll
        for (int m = 0; m < 4; m++) {
            unpack4(curA[m], xA[m]);
            unpack4(curB[m], xB[m]);
        }

        #pragma unroll
        for (int k = 0; k < 4; k++) {
            hsm[p][0][lane] = hA;
            hsm[p][1][lane] = hB;
            __syncwarp();
            const u64* hpA = (const u64*)&hsm[p][0][hsel];
            const u64* hpB = (const u64*)&hsm[p][1][hsel];
            p ^= 1;

            // chain A accumulators (2-way split) + chain B interleaved
            u64 aI0 = pk2(xA[0][k], 0.0f), aI1 = 0ull;
            u64 aF0 = pk2(xA[1][k], 0.0f), aF1 = 0ull;
            u64 aG0 = pk2(xA[2][k], 0.0f), aG1 = 0ull;
            u64 aO0 = pk2(xA[3][k], 0.0f), aO1 = 0ull;
            u64 bI0 = pk2(xB[0][k], 0.0f), bI1 = 0ull;
            u64 bF0 = pk2(xB[1][k], 0.0f), bF1 = 0ull;
            u64 bG0 = pk2(xB[2][k], 0.0f), bG1 = 0ull;
            u64 bO0 = pk2(xB[3][k], 0.0f), bO1 = 0ull;

            #pragma unroll
            for (int m = 0; m < 4; m++) {
                u64 ha = hpA[m], hb = hpB[m];
                aI0 = ffma2(ha, wp[0][m], aI0);
                aF0 = ffma2(ha, wp[1][m], aF0);
                aG0 = ffma2(ha, wp[2][m], aG0);
                aO0 = ffma2(ha, wp[3][m], aO0);
                bI0 = ffma2(hb, wp[0][m], bI0);
                bF0 = ffma2(hb, wp[1][m], bF0);
                bG0 = ffma2(hb, wp[2][m], bG0);
                bO0 = ffma2(hb, wp[3][m], bO0);
            }
            #pragma unroll
            for (int m = 4; m < 8; m++) {
                u64 ha = hpA[m], hb = hpB[m];
                aI1 = ffma2(ha, wp[0][m], aI1);
                aF1 = ffma2(ha, wp[1][m], aF1);
                aG1 = ffma2(ha, wp[2][m], aG1);
                aO1 = ffma2(ha, wp[3][m], aO1);
                bI1 = ffma2(hb, wp[0][m], bI1);
                bF1 = ffma2(hb, wp[1][m], bF1);
                bG1 = ffma2(hb, wp[2][m], bG1);
                bO1 = ffma2(hb, wp[3][m], bO1);
            }

            float ivA = sig_t(upk_sum(add2(aI0, aI1)));
            float fvA = sig_t(upk_sum(add2(aF0, aF1)));
            float gvA = fmaxf(upk_sum(add2(aG0, aG1)), 0.0f);
            float ovA = sig_t(upk_sum(add2(aO0, aO1)));
            float ivB = sig_t(upk_sum(add2(bI0, bI1)));
            float fvB = sig_t(upk_sum(add2(bF0, bF1)));
            float gvB = fmaxf(upk_sum(add2(bG0, bG1)), 0.0f);
            float ovB = sig_t(upk_sum(add2(bO0, bO1)));

            cA = fmaf(fvA, cA, ivA * gvA);
            hA = ovA * fmaxf(cA, 0.0f);
            cB = fmaf(fvB, cB, ivB * gvB);
            hB = ovB * fmaxf(cB, 0.0f);
        }

        #pragma unroll
        for (int m = 0; m < 4; m++) { curA[m] = nxtA[m]; curB[m] = nxtB[m]; }
    }

    // MLP head
    hsm[p][0][lane] = hA;
    hsm[p][1][lane] = hB;
    __syncwarp();

    if (u == 0) {
        #pragma unroll
        for (int ch = 0; ch < 2; ch++) {
            float hv[HH];
            #pragma unroll
            for (int j = 0; j < HH; j++) hv[j] = hsm[p][ch][hsel + j];

            float x2[8];
            #pragma unroll
            for (int kk = 0; kk < 8; kk++) {
                float s = b2[kk];
                #pragma unroll
                for (int j = 0; j < HH; j++) s = fmaf(hv[j], W2[j * 8 + kk], s);
                x2[kk] = fmaxf(s, 0.0f);
            }
            float x3[4];
            #pragma unroll
            for (int m = 0; m < 4; m++) {
                float s = b3[m];
                #pragma unroll
                for (int kk = 0; kk < 8; kk++) s = fmaf(x2[kk], W3[kk * 4 + m], s);
                x3[m] = fmaxf(s, 0.0f);
            }
            float s = bo[0];
            #pragma unroll
            for (int m = 0; m < 4; m++) s = fmaf(x3[m], Wo[m], s);
            out[(p0 + ch) * 2 + (hsel >> 4)] = sig_t(s);
        }
    }
}

// ---------------------------------------------------------------------------
// Launch
// ---------------------------------------------------------------------------
extern "C" void kernel_launch(void* const* d_in, const int* in_sizes, int n_in,
                              void* d_out, int out_size)
{
    const float* x  = (const float*)d_in[0];   // [B, T, F]
    const float* Wx = (const float*)d_in[1];   // [F, 4H]
    const float* Wh = (const float*)d_in[2];   // [H, 4H]
    const float* b  = (const float*)d_in[3];   // [4H]
    const float* W2 = (const float*)d_in[4];   // [H, 8]
    const float* b2 = (const float*)d_in[5];   // [8]
    const float* W3 = (const float*)d_in[6];   // [8, 4]
    const float* b3 = (const float*)d_in[7];   // [4]
    const float* Wo = (const float*)d_in[8];   // [4, 1]
    const float* bo = (const float*)d_in[9];   // [1]
    float* out = (float*)d_out;                // [B, 1]

    cudaFuncSetAttribute(xz_gemm_kernel,
                         cudaFuncAttributeMaxDynamicSharedMemorySize, SMEM_A_BYTES);
    xz_gemm_kernel<<<BT / (64 * NTILE), 256, SMEM_A_BYTES>>>(x, Wx, b);
    lstm_rec_kernel<<<BB / 4, 32>>>(Wh, W2, b2, W3, b3, Wo, bo, out);
}

// round 12
// speedup vs baseline: 1.0145x; 1.0145x over previous
#include <cuda_runtime.h>
#include <cuda_fp16.h>
#include <mma.h>

using namespace nvcuda;

// Problem constants
#define BB   2048
#define TT   512
#define FF   64
#define HH   16
#define G4   64            // 4*H
#define BT   (BB * TT)     // 1,048,576 rows of x
#define TB   (TT / 4)      // 128 t-blocks of 4 steps

// 128 MiB scratch: xz (+bias) fp16, layout [bpair][tb][row01][gate][4t]
__device__ __half g_xz[(long)BB * G4 * TT];

// ---------------------------------------------------------------------------
// helpers
// ---------------------------------------------------------------------------
typedef unsigned long long u64;
__device__ __forceinline__ u64 pk2(float lo, float hi) {
    u64 r; asm("mov.b64 %0, {%1, %2};" : "=l"(r) : "f"(lo), "f"(hi)); return r;
}
__device__ __forceinline__ float upk_sum(u64 v) {
    float lo, hi; asm("mov.b64 {%0, %1}, %2;" : "=f"(lo), "=f"(hi) : "l"(v));
    return lo + hi;
}
__device__ __forceinline__ u64 ffma2(u64 a, u64 b, u64 c) {
    u64 d; asm("fma.rn.f32x2 %0, %1, %2, %3;" : "=l"(d) : "l"(a), "l"(b), "l"(c));
    return d;
}
__device__ __forceinline__ u64 add2(u64 a, u64 b) {
    u64 d; asm("add.rn.f32x2 %0, %1, %2;" : "=l"(d) : "l"(a), "l"(b));
    return d;
}
__device__ __forceinline__ unsigned smem_u32(const void* p) {
    unsigned a;
    asm("{ .reg .u64 t; cvta.to.shared.u64 t, %1; cvt.u32.u64 %0, t; }"
        : "=r"(a) : "l"(p));
    return a;
}
__device__ __forceinline__ void cp16(unsigned dst, const void* src) {
    asm volatile("cp.async.ca.shared.global [%0], [%1], 16;" :: "r"(dst), "l"(src));
}
#define CP_COMMIT() asm volatile("cp.async.commit_group;" ::: "memory")
#define CP_WAIT0()  asm volatile("cp.async.wait_group 0;" ::: "memory")

// sigmoid(x) = 0.5*tanh(0.5x)+0.5  (1 MUFU op)
__device__ __forceinline__ float sig_t(float x) {
    float t;
    asm("tanh.approx.f32 %0, %1;" : "=f"(t) : "f"(x * 0.5f));
    return fmaf(t, 0.5f, 0.5f);
}

__device__ __forceinline__ void unpack4(uint2 v, float* o) {
    float2 q0 = __half22float2(*(__half2*)&v.x);
    float2 q1 = __half22float2(*(__half2*)&v.y);
    o[0] = q0.x; o[1] = q0.y; o[2] = q1.x; o[3] = q1.y;
}

// ---------------------------------------------------------------------------
// Kernel A: xz = x @ Wx + b (tf32 WMMA), fp16 store to [bpair][tb][row][gate][4t]
// Per block: NTILE 64-row tiles. Wx B-fragments in registers; x double-buffered
// cp.async; per-warp private transpose epilogue.
// ---------------------------------------------------------------------------
#define NTILE 16
#define PAD   72   // x staging pad (multiple of 8)
#define ZW_LD 36   // per-warp transpose pad (multiple of 4)
#define SMEM_A_BYTES ((2 * 64 * PAD + 8 * 16 * ZW_LD) * 4)   // 55296 B

__global__ __launch_bounds__(256) void xz_gemm_kernel(
    const float* __restrict__ x, const float* __restrict__ Wx,
    const float* __restrict__ bias)
{
    extern __shared__ float smem[];
    float* xs0 = smem;
    float* xs1 = smem + 64 * PAD;
    float* zw  = smem + 2 * 64 * PAD;   // Wx staging, then per-warp zs strips

    const int tid  = threadIdx.x;
    const int warp = tid >> 5;
    const int lane = tid & 31;
    const int wr   = warp >> 1;   // 0..3 -> 16-row strip
    const int wc   = warp & 1;    // 0..1 -> 32-col half

    // Stage Wx (64x64) once into zw region (PAD stride)
    const float4* wg = (const float4*)Wx;
    #pragma unroll
    for (int i = tid; i < FF * 16; i += 256) {
        int r = i >> 4, c = i & 15;
        float4 v = wg[r * 16 + c];
        float* dst = &zw[r * PAD + c * 4];
        dst[0] = v.x; dst[1] = v.y; dst[2] = v.z; dst[3] = v.w;
    }
    __syncthreads();

    // Preload all B fragments into registers (tf32)
    wmma::fragment<wmma::matrix_b, 16, 16, 8, wmma::precision::tf32, wmma::row_major> bfr[8][2];
    #pragma unroll
    for (int k = 0; k < 8; k++) {
        #pragma unroll
        for (int n = 0; n < 2; n++) {
            wmma::load_matrix_sync(bfr[k][n], &zw[(k * 8) * PAD + wc * 32 + n * 16], PAD);
            #pragma unroll
            for (int e = 0; e < bfr[k][n].num_elements; e++)
                bfr[k][n].x[e] = wmma::__float_to_tf32(bfr[k][n].x[e]);
        }
    }
    __syncthreads();   // zw free for per-warp reuse

    float* zwp = zw + warp * 16 * ZW_LD;        // this warp's private strip
    const float bg = bias[wc * 32 + lane];      // gate fixed per lane

    const long tile0 = (long)blockIdx.x * NTILE;

    // Prefetch tile 0
    {
        const float* src = x + tile0 * 64 * FF;
        unsigned dbase = smem_u32(xs0);
        #pragma unroll
        for (int j = 0; j < 4; j++) {
            int i = tid + j * 256;
            int r = i >> 4, c = i & 15;
            cp16(dbase + (unsigned)(r * PAD + c * 4) * 4, src + r * 64 + c * 4);
        }
        CP_COMMIT();
    }

    #pragma unroll 1
    for (int it = 0; it < NTILE; it++) {
        CP_WAIT0();
        __syncthreads();   // buffer `it` filled; all warps done with buffer it-1

        if (it + 1 < NTILE) {
            const float* src = x + (tile0 + it + 1) * 64 * FF;
            unsigned dbase = smem_u32(((it + 1) & 1) ? xs1 : xs0);
            #pragma unroll
            for (int j = 0; j < 4; j++) {
                int i = tid + j * 256;
                int r = i >> 4, c = i & 15;
                cp16(dbase + (unsigned)(r * PAD + c * 4) * 4, src + r * 64 + c * 4);
            }
            CP_COMMIT();
        }

        float* xb = (it & 1) ? xs1 : xs0;

        wmma::fragment<wmma::accumulator, 16, 16, 8, float> acc[2];
        wmma::fill_fragment(acc[0], 0.0f);
        wmma::fill_fragment(acc[1], 0.0f);

        #pragma unroll
        for (int k = 0; k < 8; k++) {
            wmma::fragment<wmma::matrix_a, 16, 16, 8, wmma::precision::tf32, wmma::row_major> a;
            wmma::load_matrix_sync(a, &xb[(wr * 16) * PAD + k * 8], PAD);
            #pragma unroll
            for (int e = 0; e < a.num_elements; e++) a.x[e] = wmma::__float_to_tf32(a.x[e]);
            wmma::mma_sync(acc[0], a, bfr[k][0], acc[0]);
            wmma::mma_sync(acc[1], a, bfr[k][1], acc[1]);
        }

        // Per-warp private transpose: acc patch = rows wr*16..+16, gates wc*32..+32
        wmma::store_matrix_sync(zwp,      acc[0], ZW_LD, wmma::mem_row_major);
        wmma::store_matrix_sync(zwp + 16, acc[1], ZW_LD, wmma::mem_row_major);
        __syncwarp();

        // fp16 write-out: lane owns gate wc*32+lane; 4 tb chunks of this patch
        {
            const long row0 = (tile0 + it) * 64;
            const int b  = (int)(row0 >> 9);
            const int t0 = (int)(row0 & 511);

            #pragma unroll
            for (int jj = 0; jj < 4; jj++) {
                const long tbg = (t0 >> 2) + wr * 4 + jj;
                __half* chunk = g_xz +
                    (((long)(b >> 1) * TB + tbg) * 2 + (b & 1)) * 256 +
                    (wc * 32 + lane) * 4;
                __half2 h01 = __floats2half2_rn(zwp[(jj * 4 + 0) * ZW_LD + lane] + bg,
                                                zwp[(jj * 4 + 1) * ZW_LD + lane] + bg);
                __half2 h23 = __floats2half2_rn(zwp[(jj * 4 + 2) * ZW_LD + lane] + bg,
                                                zwp[(jj * 4 + 3) * ZW_LD + lane] + bg);
                uint2 v;
                v.x = *(unsigned*)&h01;
                v.y = *(unsigned*)&h23;
                *(uint2*)chunk = v;
            }
        }
    }
}

// ---------------------------------------------------------------------------
// Kernel B: LSTM recurrence + MLP head. 4 rows per warp (2 bpair chains),
// 4 warps per block (proper SMSP distribution). Lane u computes all 4 gates
// of unit u for row (lane&16) of BOTH chains; FFMA2 split chains; smem
// double-slot h broadcast.
// ---------------------------------------------------------------------------
__global__ __launch_bounds__(128) void lstm_rec_kernel(
    const float* __restrict__ Wh,
    const float* __restrict__ W2, const float* __restrict__ b2,
    const float* __restrict__ W3, const float* __restrict__ b3,
    const float* __restrict__ Wo, const float* __restrict__ bo,
    float* __restrict__ out)
{
    __shared__ alignas(8) float hsm[4][2][2][32];   // [warp][slot][chain][lane]

    const int lane = threadIdx.x & 31;
    const int warp = threadIdx.x >> 5;
    const int u    = lane & 15;             // unit
    const int hsel = lane & 16;             // row within pair
    const int p0 = (blockIdx.x * 4 + warp) * 2;   // chain A bpair
    const int p1 = p0 + 1;                        // chain B bpair

    // Packed recurrent weights (shared by all 4 rows): wp[g][m]
    u64 wp[4][8];
    #pragma unroll
    for (int g = 0; g < 4; g++) {
        const int gate = u + 16 * g;
        #pragma unroll
        for (int m = 0; m < 8; m++)
            wp[g][m] = pk2(Wh[(2 * m) * G4 + gate], Wh[(2 * m + 1) * G4 + gate]);
    }

    const __half* baseA = g_xz + (long)p0 * (TB * 512) + (hsel >> 4) * 256 + u * 4;
    const __half* baseB = g_xz + (long)p1 * (TB * 512) + (hsel >> 4) * 256 + u * 4;

    float hA = 0.0f, cA = 0.0f, hB = 0.0f, cB = 0.0f;
    int p = 0;

    uint2 curA[4], nxtA[4], curB[4], nxtB[4];
    #pragma unroll
    for (int m = 0; m < 4; m++) {
        curA[m] = *(const uint2*)(baseA + 64 * m);
        curB[m] = *(const uint2*)(baseB + 64 * m);
    }

    #pragma unroll 1
    for (int tb = 0; tb < TB; tb++) {
        if (tb < TB - 1) {
            const __half* qa = baseA + (tb + 1) * 512;
            const __half* qb = baseB + (tb + 1) * 512;
            #pragma unroll
            for (int m = 0; m < 4; m++) {
                nxtA[m] = *(const uint2*)(qa + 64 * m);
                nxtB[m] = *(const uint2*)(qb + 64 * m);
            }
        }

        float xA[4][4], xB[4][4];   // [gate][k]
        #pragma unroll
        for (int m = 0; m < 4; m++) {
            unpack4(curA[m], xA[m]);
            unpack4(curB[m], xB[m]);
        }

        #pragma unroll
        for (int k = 0; k < 4; k++) {
            hsm[warp][p][0][lane] = hA;
            hsm[warp][p][1][lane] = hB;
            __syncwarp();
            const u64* hpA = (const u64*)&hsm[warp][p][0][hsel];
            const u64* hpB = (const u64*)&hsm[warp][p][1][hsel];
            p ^= 1;

            u64 aI0 = pk2(xA[0][k], 0.0f), aI1 = 0ull;
            u64 aF0 = pk2(xA[1][k], 0.0f), aF1 = 0ull;
            u64 aG0 = pk2(xA[2][k], 0.0f), aG1 = 0ull;
            u64 aO0 = pk2(xA[3][k], 0.0f), aO1 = 0ull;
            u64 bI0 = pk2(xB[0][k], 0.0f), bI1 = 0ull;
            u64 bF0 = pk2(xB[1][k], 0.0f), bF1 = 0ull;
            u64 bG0 = pk2(xB[2][k], 0.0f), bG1 = 0ull;
            u64 bO0 = pk2(xB[3][k], 0.0f), bO1 = 0ull;

            #pragma unroll
            for (int m = 0; m < 4; m++) {
                u64 ha = hpA[m], hb = hpB[m];
                aI0 = ffma2(ha, wp[0][m], aI0);
                aF0 = ffma2(ha, wp[1][m], aF0);
                aG0 = ffma2(ha, wp[2][m], aG0);
                aO0 = ffma2(ha, wp[3][m], aO0);
                bI0 = ffma2(hb, wp[0][m], bI0);
                bF0 = ffma2(hb, wp[1][m], bF0);
                bG0 = ffma2(hb, wp[2][m], bG0);
                bO0 = ffma2(hb, wp[3][m], bO0);
            }
            #pragma unroll
            for (int m = 4; m < 8; m++) {
                u64 ha = hpA[m], hb = hpB[m];
                aI1 = ffma2(ha, wp[0][m], aI1);
                aF1 = ffma2(ha, wp[1][m], aF1);
                aG1 = ffma2(ha, wp[2][m], aG1);
                aO1 = ffma2(ha, wp[3][m], aO1);
                bI1 = ffma2(hb, wp[0][m], bI1);
                bF1 = ffma2(hb, wp[1][m], bF1);
                bG1 = ffma2(hb, wp[2][m], bG1);
                bO1 = ffma2(hb, wp[3][m], bO1);
            }

            float ivA = sig_t(upk_sum(add2(aI0, aI1)));
            float fvA = sig_t(upk_sum(add2(aF0, aF1)));
            float gvA = fmaxf(upk_sum(add2(aG0, aG1)), 0.0f);
            float ovA = sig_t(upk_sum(add2(aO0, aO1)));
            float ivB = sig_t(upk_sum(add2(bI0, bI1)));
            float fvB = sig_t(upk_sum(add2(bF0, bF1)));
            float gvB = fmaxf(upk_sum(add2(bG0, bG1)), 0.0f);
            float ovB = sig_t(upk_sum(add2(bO0, bO1)));

            cA = fmaf(fvA, cA, ivA * gvA);
            hA = ovA * fmaxf(cA, 0.0f);
            cB = fmaf(fvB, cB, ivB * gvB);
            hB = ovB * fmaxf(cB, 0.0f);
        }

        #pragma unroll
        for (int m = 0; m < 4; m++) { curA[m] = nxtA[m]; curB[m] = nxtB[m]; }
    }

    // MLP head
    hsm[warp][p][0][lane] = hA;
    hsm[warp][p][1][lane] = hB;
    __syncwarp();

    if (u == 0) {
        #pragma unroll
        for (int ch = 0; ch < 2; ch++) {
            float hv[HH];
            #pragma unroll
            for (int j = 0; j < HH; j++) hv[j] = hsm[warp][p][ch][hsel + j];

            float x2[8];
            #pragma unroll
            for (int kk = 0; kk < 8; kk++) {
                float s = b2[kk];
                #pragma unroll
                for (int j = 0; j < HH; j++) s = fmaf(hv[j], W2[j * 8 + kk], s);
                x2[kk] = fmaxf(s, 0.0f);
            }
            float x3[4];
            #pragma unroll
            for (int m = 0; m < 4; m++) {
                float s = b3[m];
                #pragma unroll
                for (int kk = 0; kk < 8; kk++) s = fmaf(x2[kk], W3[kk * 4 + m], s);
                x3[m] = fmaxf(s, 0.0f);
            }
            float s = bo[0];
            #pragma unroll
            for (int m = 0; m < 4; m++) s = fmaf(x3[m], Wo[m], s);
            out[(p0 + ch) * 2 + (hsel >> 4)] = sig_t(s);
        }
    }
}

// ---------------------------------------------------------------------------
// Launch
// ---------------------------------------------------------------------------
extern "C" void kernel_launch(void* const* d_in, const int* in_sizes, int n_in,
                              void* d_out, int out_size)
{
    const float* x  = (const float*)d_in[0];   // [B, T, F]
    const float* Wx = (const float*)d_in[1];   // [F, 4H]
    const float* Wh = (const float*)d_in[2];   // [H, 4H]
    const float* b  = (const float*)d_in[3];   // [4H]
    const float* W2 = (const float*)d_in[4];   // [H, 8]
    const float* b2 = (const float*)d_in[5];   // [8]
    const float* W3 = (const float*)d_in[6];   // [8, 4]
    const float* b3 = (const float*)d_in[7];   // [4]
    const float* Wo = (const float*)d_in[8];   // [4, 1]
    const float* bo = (const float*)d_in[9];   // [1]
    float* out = (float*)d_out;                // [B, 1]

    cudaFuncSetAttribute(xz_gemm_kernel,
                         cudaFuncAttributeMaxDynamicSharedMemorySize, SMEM_A_BYTES);
    xz_gemm_kernel<<<BT / (64 * NTILE), 256, SMEM_A_BYTES>>>(x, Wx, b);
    lstm_rec_kernel<<<BB / 16, 128>>>(Wh, W2, b2, W3, b3, Wo, bo, out);
}